// round 16
// baseline (speedup 1.0000x reference)
#include <cuda_runtime.h>

#define T_DIM 512
#define B_DIM 256
#define N_DIM 128
#define BN    (B_DIM * N_DIM)
#define NCHUNK 128
#define TCHUNK (T_DIM / NCHUNK)
#define NFCTA  148
#define SLOTS  3

#define LOGC_F 5.545177444479562f    /* ln 256 */
#define LOGC_D 5.545177444479562

__device__ float g_score[B_DIM];
__device__ float g_logZ[B_DIM];
__device__ int   g_len[B_DIM];
__device__ float g_part_s[NCHUNK * B_DIM];
__device__ int   g_part_c[NCHUNK * B_DIM];
__device__ int   g_units[B_DIM];          /* b sorted by len desc */
__device__ float g_vec[2][B_DIM][N_DIM];  /* meeting vectors */
__device__ float g_acc[2][B_DIM];         /* accumulated log scales */
__device__ int   g_ctr[2];                /* unit pop counters (self-reset) */
__device__ int   g_pairdone[B_DIM];       /* per-b arrival (self-reset) */
__device__ unsigned int g_done;           /* CTA completion (self-reset) */
__device__ unsigned int g_a1done;         /* score-chunk completion (self-reset) */
__device__ volatile int g_ready;          /* schedule ready flag (self-reset) */

// ---------------- f32x2 helpers ----------------
__device__ __forceinline__ unsigned long long pack2(float lo, float hi) {
    unsigned long long u;
    asm("mov.b64 %0, {%1,%2};" : "=l"(u) : "f"(lo), "f"(hi));
    return u;
}
__device__ __forceinline__ void unpack2(unsigned long long u, float& lo, float& hi) {
    asm("mov.b64 {%0,%1}, %2;" : "=f"(lo), "=f"(hi) : "l"(u));
}
__device__ __forceinline__ void ffma2(unsigned long long& d,
                                      unsigned long long a, unsigned long long b) {
    asm("fma.rn.f32x2 %0, %1, %2, %0;" : "+l"(d) : "l"(a), "l"(b));
}

// ---------------------------------------------------------------------------
// Single fused kernel: 148 CTAs x 384 threads = 3 chain slots x 128 threads
// (3 warps/SMSP -> 3 independent serial chains cross-hide latency).
// Phase 1: CTAs 0..127 compute score partials (threads 0..255).
// Phase 2: all CTAs load E2 registers (overlaps score tail).
// Phase 3: last scorer CTA combines + bitonic-sorts -> g_ready.
// Phase 4: forward loop. Thread owns ONE j, FULL K: E = 64 f32x2 regs,
//          per step 32 LDS.128 + 64 FFMA2, NO shfl, 1 bar/step.
//          x2-unrolled static ping-pong, 2-deep emit ring (no local mem).
//          Renorm every 64 steps. Work-stealing over 512 half-units (LPT).
// Phase 5: last CTA does fused (logZ-score)/B reduction + full state reset.
// ---------------------------------------------------------------------------
__global__ void __launch_bounds__(384, 1)
crf_kernel(const float* __restrict__ emit,
           const int*   __restrict__ target,
           const int*   __restrict__ mask,
           const float* __restrict__ trans,
           const float* __restrict__ strans,
           const float* __restrict__ etrans,
           float* __restrict__ out) {
    __shared__ __align__(16) float pbuf[SLOTS][2][N_DIM];
    __shared__ float  wsum[SLOTS][4];
    __shared__ int    s_idx[SLOTS];
    __shared__ int    s_old[SLOTS];
    __shared__ int    sflag;
    __shared__ int    skey[B_DIM];
    __shared__ double shd[B_DIM];

    const int tid    = threadIdx.x;
    const int lane   = tid & 31;
    const int slot   = tid >> 7;              // 0..2
    const int stid   = tid & 127;
    const int j      = stid;                  // one output tag per thread
    const int swarp  = stid >> 5;             // 0..3 within slot
    const int sg     = blockIdx.x * SLOTS + slot;
    const int orient = sg & 1;                // 0 = fwd, 1 = bwd

    // ================= Phase 1: score partials (CTAs 0..127) ==============
    bool amLastScorer = false;
    if (blockIdx.x < NCHUNK) {
        if (tid < B_DIM) {
            const int b = tid;
            const int t0 = blockIdx.x * TCHUNK;
            float s = 0.f; int cnt = 0;
            #pragma unroll
            for (int t = t0; t < t0 + TCHUNK; ++t) {
                if (mask[t * B_DIM + b] != 0) {
                    int tg = target[t * B_DIM + b];
                    float v = emit[(size_t)t * BN + b * N_DIM + tg];
                    if (t > 0) {
                        int tp = target[(t - 1) * B_DIM + b];
                        v += trans[tp * N_DIM + tg];
                    }
                    s += v; cnt += 1;
                }
            }
            g_part_s[blockIdx.x * B_DIM + b] = s;
            g_part_c[blockIdx.x * B_DIM + b] = cnt;
        }
        __threadfence();
        __syncthreads();
        if (tid == 0) {
            unsigned int old = atomicAdd(&g_a1done, 1u);
            sflag = (old == NCHUNK - 1) ? 1 : 0;
        }
        __syncthreads();
        amLastScorer = (sflag != 0);
    }

    // ================= Phase 2: load E2 registers (all CTAs) ===============
    // fwd: column j, i-pair packed: E2[m] = (e^A[2m][j], e^A[2m+1][j])
    // bwd: row j:                   E2[m] = (e^A[j][2m], e^A[j][2m+1])
    unsigned long long E2[64];
    if (orient == 0) {
        #pragma unroll
        for (int m = 0; m < 64; ++m)
            E2[m] = pack2(__expf(trans[(2 * m) * N_DIM + j]),
                          __expf(trans[(2 * m + 1) * N_DIM + j]));
    } else {
        const float* tr = trans + j * N_DIM;
        #pragma unroll
        for (int m = 0; m < 64; ++m)
            E2[m] = pack2(__expf(tr[2 * m]), __expf(tr[2 * m + 1]));
    }

    // ================= Phase 3: combine + sort (last scorer CTA) ===========
    if (amLastScorer) {
        __threadfence();
        if (tid < B_DIM) {
            const int b = tid;
            float s = 0.f; int cnt = 0;
            for (int cc = 0; cc < NCHUNK; ++cc) {
                s   += g_part_s[cc * B_DIM + b];
                cnt += g_part_c[cc * B_DIM + b];
            }
            s += strans[target[b]];
            s += etrans[target[(cnt - 1) * B_DIM + b]];
            g_score[b] = s;
            g_len[b]   = cnt;
            skey[b] = (cnt << 9) | b;
        }
        __syncthreads();
        for (int k = 2; k <= B_DIM; k <<= 1) {
            for (int jj = k >> 1; jj > 0; jj >>= 1) {
                if (tid < B_DIM) {
                    int p = tid ^ jj;
                    if (p > tid) {
                        int a0 = skey[tid], a1 = skey[p];
                        bool desc = ((tid & k) != 0);
                        if ((a0 > a1) == desc) { skey[tid] = a1; skey[p] = a0; }
                    }
                }
                __syncthreads();
            }
        }
        if (tid < B_DIM) g_units[tid] = skey[tid] & 511;
        __threadfence();
        __syncthreads();
        if (tid == 0) { g_a1done = 0; g_ready = 1; }
    } else {
        if (tid == 0) { while (g_ready == 0) { __nanosleep(64); } }
        __syncthreads();
        __threadfence();
    }

    // ================= Phase 4: forward loop ===============================
    float* pb0 = pbuf[slot][0];
    float* pb1 = pbuf[slot][1];
    float v;

    #define BARS() asm volatile("bar.sync %0, 128;" :: "r"(slot + 1) : "memory")

    #define STEP(EC, PR, PW, TT) do {                                        \
        float eev = ((TT) == lastSpec) ? 1.f : __expf((EC) - LOGC_F);        \
        const ulonglong2* pu = (const ulonglong2*)(PR);                      \
        unsigned long long a0 = 0ull, a1 = 0ull, a2 = 0ull, a3 = 0ull;       \
        _Pragma("unroll")                                                    \
        for (int k = 0; k < 32; k += 2) {                                    \
            ulonglong2 x = pu[k];                                            \
            ulonglong2 y = pu[k + 1];                                        \
            ffma2(a0, x.x, E2[2 * k]);                                       \
            ffma2(a1, x.y, E2[2 * k + 1]);                                   \
            ffma2(a2, y.x, E2[2 * k + 2]);                                   \
            ffma2(a3, y.y, E2[2 * k + 3]);                                   \
        }                                                                    \
        float f0, f1, f2, f3, f4, f5, f6, f7;                                \
        unpack2(a0, f0, f1); unpack2(a1, f2, f3);                            \
        unpack2(a2, f4, f5); unpack2(a3, f6, f7);                            \
        v = (((f0 + f1) + (f2 + f3)) + ((f4 + f5) + (f6 + f7))) * eev;       \
        if (((TT) & 63) == 0) {                                              \
            float r = v;                                                     \
            _Pragma("unroll")                                                \
            for (int o = 16; o; o >>= 1)                                     \
                r += __shfl_xor_sync(0xffffffffu, r, o);                     \
            if (lane == 0) wsum[slot][swarp] = r;                            \
            BARS();                                                          \
            float ss = (wsum[slot][0] + wsum[slot][1])                       \
                     + (wsum[slot][2] + wsum[slot][3]);                      \
            v *= (1.f / ss);                                                 \
            acc_log += __logf(ss);                                           \
        }                                                                    \
        (PW)[j] = v;                                                         \
        BARS();                                                              \
    } while (0)

    for (;;) {
        if (stid == 0) s_idx[slot] = atomicAdd(&g_ctr[orient], 1);
        BARS();
        const int idx = s_idx[slot];
        if (idx >= B_DIM) break;

        const int b   = g_units[idx];
        const int len = g_len[b];
        const int m   = (len - 1) >> 1;
        const int nsteps   = orient ? (len - 1 - m) : m;
        const int lastSpec = orient ? nsteps : -1;
        const int e0i      = orient ? (len - 1) : 0;
        const int estep    = orient ? -1 : 1;
        const float* eb    = emit + b * N_DIM + j;

        float acc_log = 0.f;
        if (orient == 0) {
            v = __expf(strans[j] + eb[0]);
        } else if (nsteps == 0) {
            v = __expf(etrans[j]);
        } else {
            v = __expf(eb[(size_t)(len - 1) * BN] + etrans[j] - LOGC_F);
        }

        if (nsteps > 0) {
            pb0[j] = v;
            #define LDE(TT) eb[(size_t)max(0, min(len - 1, e0i + estep * (TT))) * BN]
            float e0 = LDE(1), e1 = LDE(2);
            BARS();
            int t = 1;
            #pragma unroll 1
            for (; t + 1 <= nsteps; t += 2) {
                float n0 = LDE(t + 2), n1 = LDE(t + 3);
                STEP(e0, pb0, pb1, t);
                STEP(e1, pb1, pb0, t + 1);
                e0 = n0; e1 = n1;
            }
            if (t <= nsteps) { STEP(e0, pb0, pb1, t); }
            #undef LDE
        }

        // publish this half; second finisher computes the meeting dot.
        g_vec[orient][b][j] = v;
        if (stid == 0) g_acc[orient][b] = acc_log;
        __threadfence();
        BARS();
        if (stid == 0) s_old[slot] = atomicAdd(&g_pairdone[b], 1);
        BARS();
        if (s_old[slot] == 1) {
            __threadfence();
            float r = v * g_vec[orient ^ 1][b][j];
            #pragma unroll
            for (int o = 16; o; o >>= 1)
                r += __shfl_xor_sync(0xffffffffu, r, o);
            if (lane == 0) wsum[slot][swarp] = r;
            BARS();
            if (stid == 0) {
                float dot = (wsum[slot][0] + wsum[slot][1])
                          + (wsum[slot][2] + wsum[slot][3]);
                g_logZ[b] = (float)((double)acc_log
                                    + (double)g_acc[orient ^ 1][b]
                                    + (double)(len - 1) * LOGC_D
                                    + log((double)dot));
            }
            BARS();
        }
    }
    #undef STEP
    #undef BARS

    // ================= Phase 5: fused reduction + full state reset =========
    __syncthreads();
    if (tid == 0) {
        __threadfence();
        unsigned int old = atomicAdd(&g_done, 1u);
        sflag = (old == NFCTA - 1) ? 1 : 0;
    }
    __syncthreads();
    if (sflag) {
        __threadfence();
        if (tid < 128) {
            shd[tid]       = (double)g_logZ[tid]       - (double)g_score[tid];
            shd[tid + 128] = (double)g_logZ[tid + 128] - (double)g_score[tid + 128];
            g_pairdone[tid]       = 0;
            g_pairdone[tid + 128] = 0;
        }
        if (tid < 2) g_ctr[tid] = 0;
        __syncthreads();
        for (int o = 128; o; o >>= 1) {
            if (tid < o) shd[tid] += shd[tid + o];
            __syncthreads();
        }
        if (tid == 0) {
            out[0] = (float)(shd[0] / (double)B_DIM);
            g_ready = 0;                        // self-reset for graph replay
            g_done  = 0;
        }
    }
}

extern "C" void kernel_launch(void* const* d_in, const int* in_sizes, int n_in,
                              void* d_out, int out_size) {
    const float* emit   = (const float*)d_in[0];
    const int*   target = (const int*)d_in[1];
    const int*   mask   = (const int*)d_in[2];
    const float* trans  = (const float*)d_in[3];
    const float* strans = (const float*)d_in[4];
    const float* etrans = (const float*)d_in[5];

    crf_kernel<<<NFCTA, 384>>>(emit, target, mask, trans, strans, etrans,
                               (float*)d_out);
}

// round 17
// speedup vs baseline: 1.3954x; 1.3954x over previous
#include <cuda_runtime.h>

#define T_DIM 512
#define B_DIM 256
#define N_DIM 128
#define BN    (B_DIM * N_DIM)
#define NCHUNK 128
#define TCHUNK (T_DIM / NCHUNK)
#define NFCTA  148
#define SLOTS  2
#define PSTR   68                    /* 64 floats + 16B pad per K-half */

#define LOGC_F 5.545177444479562f    /* ln 256 */
#define LOGC_D 5.545177444479562

__device__ float g_score[B_DIM];
__device__ float g_logZ[B_DIM];
__device__ int   g_len[B_DIM];
__device__ float g_part_s[NCHUNK * B_DIM];
__device__ int   g_part_c[NCHUNK * B_DIM];
__device__ int   g_units[B_DIM];          /* b sorted by len desc */
__device__ float g_vec[2][B_DIM][N_DIM];  /* meeting vectors */
__device__ float g_acc[2][B_DIM];         /* accumulated log scales */
__device__ int   g_ctr[2];                /* unit pop counters (self-reset) */
__device__ int   g_pairdone[B_DIM];       /* per-b arrival (self-reset) */
__device__ unsigned int g_done;           /* CTA completion (self-reset) */
__device__ unsigned int g_a1done;         /* score-chunk completion (self-reset) */
__device__ volatile int g_ready;          /* schedule ready flag (self-reset) */

// ---------------- f32x2 helpers ----------------
__device__ __forceinline__ unsigned long long pack2(float lo, float hi) {
    unsigned long long u;
    asm("mov.b64 %0, {%1,%2};" : "=l"(u) : "f"(lo), "f"(hi));
    return u;
}
__device__ __forceinline__ void unpack2(unsigned long long u, float& lo, float& hi) {
    asm("mov.b64 {%0,%1}, %2;" : "=f"(lo), "=f"(hi) : "l"(u));
}
__device__ __forceinline__ void ffma2(unsigned long long& d,
                                      unsigned long long a, unsigned long long b) {
    asm("fma.rn.f32x2 %0, %1, %2, %0;" : "+l"(d) : "l"(a), "l"(b));
}

// ---------------------------------------------------------------------------
// Single fused kernel: 148 CTAs x 256 threads = 2 chain slots x 128 threads.
// Phase 1: CTAs 0..127 compute score partials for their t-chunk.
// Phase 2: all CTAs load E2 registers (overlaps the score tail).
// Phase 3: last scorer CTA combines + bitonic-sorts -> g_ready.
// Phase 4: forward loop: thread owns 2 j's over a K-half; E in 128 regs;
//          per step 16 LDS.128 + 64 FFMA2 in EIGHT 8-deep chains + 1 bar.
//          Renorm every 64 steps. Work-stealing over 512 half-units (LPT).
// Phase 5: last CTA does fused (logZ-score)/B reduction + full state reset.
// ---------------------------------------------------------------------------
__global__ void __launch_bounds__(256, 1)
crf_kernel(const float* __restrict__ emit,
           const int*   __restrict__ target,
           const int*   __restrict__ mask,
           const float* __restrict__ trans,
           const float* __restrict__ strans,
           const float* __restrict__ etrans,
           float* __restrict__ out) {
    __shared__ __align__(16) float pbuf[SLOTS][2][2 * PSTR];
    __shared__ float  wsum[SLOTS][4];
    __shared__ int    s_idx[SLOTS];
    __shared__ int    s_old[SLOTS];
    __shared__ int    sflag;
    __shared__ int    skey[B_DIM];
    __shared__ double shd[B_DIM];

    const int tid    = threadIdx.x;
    const int lane   = tid & 31;
    const int slot   = tid >> 7;              // 0..1
    const int stid   = tid & 127;
    const int h      = stid & 1;              // K-half
    const int jp     = stid >> 1;             // 0..63
    const int j0     = 2 * jp, j1 = j0 + 1;
    const int swarp  = stid >> 5;             // 0..3 within slot
    const int sg     = blockIdx.x * SLOTS + slot;
    const int orient = sg & 1;                // 0 = fwd, 1 = bwd
    const int widx   = j0 + ((j0 >> 6) << 2); // padded store index for p[j0]

    // ================= Phase 1: score partials (CTAs 0..127) ==============
    bool amLastScorer = false;
    if (blockIdx.x < NCHUNK) {
        const int b = tid;
        const int t0 = blockIdx.x * TCHUNK;
        float s = 0.f; int cnt = 0;
        #pragma unroll
        for (int t = t0; t < t0 + TCHUNK; ++t) {
            if (mask[t * B_DIM + b] != 0) {
                int tg = target[t * B_DIM + b];
                float v = emit[(size_t)t * BN + b * N_DIM + tg];
                if (t > 0) {
                    int tp = target[(t - 1) * B_DIM + b];
                    v += trans[tp * N_DIM + tg];
                }
                s += v; cnt += 1;
            }
        }
        g_part_s[blockIdx.x * B_DIM + b] = s;
        g_part_c[blockIdx.x * B_DIM + b] = cnt;
        __threadfence();
        __syncthreads();
        if (tid == 0) {
            unsigned int old = atomicAdd(&g_a1done, 1u);
            sflag = (old == NCHUNK - 1) ? 1 : 0;
        }
        __syncthreads();
        amLastScorer = (sflag != 0);
    }

    // ================= Phase 2: load E2 registers (all CTAs) ===============
    unsigned long long E2A[32], E2B[32];
    if (orient == 0) {
        #pragma unroll
        for (int m = 0; m < 32; ++m) {
            int i = 64 * h + 2 * m;
            E2A[m] = pack2(__expf(trans[i * N_DIM + j0]),
                           __expf(trans[(i + 1) * N_DIM + j0]));
            E2B[m] = pack2(__expf(trans[i * N_DIM + j1]),
                           __expf(trans[(i + 1) * N_DIM + j1]));
        }
    } else {
        #pragma unroll
        for (int m = 0; m < 32; ++m) {
            int i = 64 * h + 2 * m;
            E2A[m] = pack2(__expf(trans[j0 * N_DIM + i]),
                           __expf(trans[j0 * N_DIM + i + 1]));
            E2B[m] = pack2(__expf(trans[j1 * N_DIM + i]),
                           __expf(trans[j1 * N_DIM + i + 1]));
        }
    }
    const float sj0  = strans[j0], sj1 = strans[j1];
    const float etj0 = etrans[j0], etj1 = etrans[j1];

    // ================= Phase 3: combine + sort (last scorer CTA) ===========
    if (amLastScorer) {
        __threadfence();
        const int b = tid;
        float s = 0.f; int cnt = 0;
        for (int cc = 0; cc < NCHUNK; ++cc) {
            s   += g_part_s[cc * B_DIM + b];
            cnt += g_part_c[cc * B_DIM + b];
        }
        s += strans[target[b]];
        s += etrans[target[(cnt - 1) * B_DIM + b]];
        g_score[b] = s;
        g_len[b]   = cnt;
        skey[b] = (cnt << 9) | b;
        __syncthreads();
        for (int k = 2; k <= B_DIM; k <<= 1) {
            for (int jj = k >> 1; jj > 0; jj >>= 1) {
                int p = b ^ jj;
                if (p > b) {
                    int a0 = skey[b], a1 = skey[p];
                    bool desc = ((b & k) != 0);
                    if ((a0 > a1) == desc) { skey[b] = a1; skey[p] = a0; }
                }
                __syncthreads();
            }
        }
        g_units[b] = skey[b] & 511;
        __threadfence();
        __syncthreads();
        if (tid == 0) { g_a1done = 0; g_ready = 1; }
    } else {
        if (tid == 0) { while (g_ready == 0) { __nanosleep(64); } }
        __syncthreads();
        __threadfence();
    }

    // ================= Phase 4: forward loop ===============================
    float* pb0 = pbuf[slot][0];
    float* pb1 = pbuf[slot][1];
    const int roff = 17 * h;                  // ulonglong2 offset of my K-half

    float v0, v1;

    #define BARS() asm volatile("bar.sync %0, 128;" :: "r"(slot + 1) : "memory")

    // 8 independent 8-deep FFMA2 chains (chain id = (k&1)*2 + pair-lane)
    #define STEP(ECRAW, PR, PW, TT) do {                                     \
        float ee = ((TT) == lastSpec) ? 0.f : ((ECRAW).x - LOGC_F);          \
        float ef = ((TT) == lastSpec) ? 0.f : ((ECRAW).y - LOGC_F);          \
        float ee0 = __expf(ee), ee1 = __expf(ef);                            \
        const ulonglong2* pu = (const ulonglong2*)(PR) + roff;               \
        unsigned long long aA0 = 0ull, aA1 = 0ull, aA2 = 0ull, aA3 = 0ull;   \
        unsigned long long aB0 = 0ull, aB1 = 0ull, aB2 = 0ull, aB3 = 0ull;   \
        _Pragma("unroll")                                                    \
        for (int k = 0; k < 16; k += 2) {                                    \
            ulonglong2 x = pu[k];                                            \
            ulonglong2 y = pu[k + 1];                                        \
            ffma2(aA0, x.x, E2A[2 * k]);                                     \
            ffma2(aA1, x.y, E2A[2 * k + 1]);                                 \
            ffma2(aB0, x.x, E2B[2 * k]);                                     \
            ffma2(aB1, x.y, E2B[2 * k + 1]);                                 \
            ffma2(aA2, y.x, E2A[2 * k + 2]);                                 \
            ffma2(aA3, y.y, E2A[2 * k + 3]);                                 \
            ffma2(aB2, y.x, E2B[2 * k + 2]);                                 \
            ffma2(aB3, y.y, E2B[2 * k + 3]);                                 \
        }                                                                    \
        float f0, f1, f2, f3, f4, f5, f6, f7;                                \
        float g0, g1, g2, g3, g4, g5, g6, g7;                                \
        unpack2(aA0, f0, f1); unpack2(aA1, f2, f3);                          \
        unpack2(aA2, f4, f5); unpack2(aA3, f6, f7);                          \
        unpack2(aB0, g0, g1); unpack2(aB1, g2, g3);                          \
        unpack2(aB2, g4, g5); unpack2(aB3, g6, g7);                          \
        float s0 = ((f0 + f1) + (f2 + f3)) + ((f4 + f5) + (f6 + f7));        \
        float s1 = ((g0 + g1) + (g2 + g3)) + ((g4 + g5) + (g6 + g7));        \
        s0 += __shfl_xor_sync(0xffffffffu, s0, 1);                           \
        s1 += __shfl_xor_sync(0xffffffffu, s1, 1);                           \
        v0 = s0 * ee0; v1 = s1 * ee1;                                        \
        if (((TT) & 63) == 0) {                                              \
            float r = h ? 0.f : (v0 + v1);                                   \
            _Pragma("unroll")                                                \
            for (int o = 16; o; o >>= 1)                                     \
                r += __shfl_xor_sync(0xffffffffu, r, o);                     \
            if (lane == 0) wsum[slot][swarp] = r;                            \
            BARS();                                                          \
            float ss = (wsum[slot][0] + wsum[slot][1])                       \
                     + (wsum[slot][2] + wsum[slot][3]);                      \
            float inv = 1.f / ss;                                            \
            v0 *= inv; v1 *= inv;                                            \
            acc_log += __logf(ss);                                           \
        }                                                                    \
        if (h == 0) *(float2*)&(PW)[widx] = make_float2(v0, v1);             \
        BARS();                                                              \
    } while (0)

    for (;;) {
        if (stid == 0) s_idx[slot] = atomicAdd(&g_ctr[orient], 1);
        BARS();
        const int idx = s_idx[slot];
        if (idx >= B_DIM) break;

        const int b   = g_units[idx];
        const int len = g_len[b];
        const int m   = (len - 1) >> 1;
        const int nsteps   = orient ? (len - 1 - m) : m;
        const int lastSpec = orient ? nsteps : -1;
        const int e0i      = orient ? (len - 1) : 0;
        const int estep    = orient ? -1 : 1;
        const float* eb    = emit + b * N_DIM + j0;

        float acc_log = 0.f;
        if (orient == 0) {
            float2 e0v = *(const float2*)eb;
            v0 = __expf(sj0 + e0v.x);
            v1 = __expf(sj1 + e0v.y);
        } else if (nsteps == 0) {
            v0 = __expf(etj0);
            v1 = __expf(etj1);
        } else {
            float2 e0v = *(const float2*)(eb + (size_t)(len - 1) * BN);
            v0 = __expf(e0v.x + etj0 - LOGC_F);
            v1 = __expf(e0v.y + etj1 - LOGC_F);
        }

        if (nsteps > 0) {
            if (h == 0) *(float2*)&pb0[widx] = make_float2(v0, v1);
            #define LDE(TT) (*(const float2*)(eb + (size_t)max(0, min(len - 1, e0i + estep * (TT))) * BN))
            float2 e0 = LDE(1), e1 = LDE(2), e2 = LDE(3), e3 = LDE(4);
            BARS();
            int t = 1;
            #pragma unroll 1
            for (; t + 3 <= nsteps; t += 4) {
                float2 n0 = LDE(t + 4), n1 = LDE(t + 5),
                       n2 = LDE(t + 6), n3 = LDE(t + 7);
                STEP(e0, pb0, pb1, t);
                STEP(e1, pb1, pb0, t + 1);
                STEP(e2, pb0, pb1, t + 2);
                STEP(e3, pb1, pb0, t + 3);
                e0 = n0; e1 = n1; e2 = n2; e3 = n3;
            }
            if (t <= nsteps) { STEP(e0, pb0, pb1, t); ++t; }
            if (t <= nsteps) { STEP(e1, pb1, pb0, t); ++t; }
            if (t <= nsteps) { STEP(e2, pb0, pb1, t); }
            #undef LDE
        }

        // publish this half; second finisher computes the meeting dot.
        if (h == 0) {
            g_vec[orient][b][j0] = v0;
            g_vec[orient][b][j1] = v1;
            if (stid == 0) g_acc[orient][b] = acc_log;
        }
        __threadfence();
        BARS();
        if (stid == 0) s_old[slot] = atomicAdd(&g_pairdone[b], 1);
        BARS();
        if (s_old[slot] == 1) {
            __threadfence();
            float r = h ? 0.f : (v0 * g_vec[orient ^ 1][b][j0]
                               + v1 * g_vec[orient ^ 1][b][j1]);
            #pragma unroll
            for (int o = 16; o; o >>= 1)
                r += __shfl_xor_sync(0xffffffffu, r, o);
            if (lane == 0) wsum[slot][swarp] = r;
            BARS();
            if (stid == 0) {
                float dot = (wsum[slot][0] + wsum[slot][1])
                          + (wsum[slot][2] + wsum[slot][3]);
                g_logZ[b] = (float)((double)acc_log
                                    + (double)g_acc[orient ^ 1][b]
                                    + (double)(len - 1) * LOGC_D
                                    + log((double)dot));
            }
            BARS();
        }
    }
    #undef STEP
    #undef BARS

    // ================= Phase 5: fused reduction + full state reset =========
    __syncthreads();
    if (tid == 0) {
        __threadfence();
        unsigned int old = atomicAdd(&g_done, 1u);
        sflag = (old == NFCTA - 1) ? 1 : 0;
    }
    __syncthreads();
    if (sflag) {
        __threadfence();
        if (tid < 128) {
            shd[tid]       = (double)g_logZ[tid]       - (double)g_score[tid];
            shd[tid + 128] = (double)g_logZ[tid + 128] - (double)g_score[tid + 128];
            g_pairdone[tid]       = 0;
            g_pairdone[tid + 128] = 0;
        }
        if (tid < 2) g_ctr[tid] = 0;
        __syncthreads();
        for (int o = 128; o; o >>= 1) {
            if (tid < o) shd[tid] += shd[tid + o];
            __syncthreads();
        }
        if (tid == 0) {
            out[0] = (float)(shd[0] / (double)B_DIM);
            g_ready = 0;                        // self-reset for graph replay
            g_done  = 0;
        }
    }
}

extern "C" void kernel_launch(void* const* d_in, const int* in_sizes, int n_in,
                              void* d_out, int out_size) {
    const float* emit   = (const float*)d_in[0];
    const int*   target = (const int*)d_in[1];
    const int*   mask   = (const int*)d_in[2];
    const float* trans  = (const float*)d_in[3];
    const float* strans = (const float*)d_in[4];
    const float* etrans = (const float*)d_in[5];

    crf_kernel<<<NFCTA, 256>>>(emit, target, mask, trans, strans, etrans,
                               (float*)d_out);
}